// round 12
// baseline (speedup 1.0000x reference)
#include <cuda_runtime.h>
#include <math.h>

#define NSTEPS 64
#define BM     32
#define GRID   256   // 8192 / 32

// Tsit5 tableau in constant memory
__constant__ float c_A[6][5] = {
    {0.f, 0.f, 0.f, 0.f, 0.f},
    {0.161f, 0.f, 0.f, 0.f, 0.f},
    {-0.008480655492356989f, 0.335480655492357f, 0.f, 0.f, 0.f},
    {2.8971530571054935f, -6.359448489975075f, 4.3622954328695815f, 0.f, 0.f},
    {5.325864828439257f, -11.748883564062828f, 7.4955393428898365f, -0.09249506636175525f, 0.f},
    {5.86145544294642f, -12.92096931784711f, 8.159367898576159f, -0.071584973281401f, -0.028269050394068383f},
};
__constant__ float c_B[6] = {
    0.09646076681806523f, 0.01f, 0.4798896504144996f,
    1.379008574103742f, -3.290069515436081f, 2.324710524099774f
};

// k stages in global scratch (L2-resident, 25 MB), strictly thread-local access
__device__ float g_k[6 * 8192 * 128];

// SMEM (floats) per CTA: sXT[32*128] | sH[32*512] | sW[2*32*128]  = 112 KB
#define OFF_XT 0
#define OFF_H  4096
#define OFF_W  20480
#define SMEM_FLOATS 28672   // 112 KB -> 2 CTAs/SM

typedef unsigned long long u64t;

__device__ __forceinline__ void cp16(float* dst, const float* src) {
    unsigned d = (unsigned)__cvta_generic_to_shared(dst);
    asm volatile("cp.async.cg.shared.global [%0], [%1], 16;" :: "r"(d), "l"(src));
}
__device__ __forceinline__ void cp_commit() { asm volatile("cp.async.commit_group;"); }
__device__ __forceinline__ void cp_wait0()  { asm volatile("cp.async.wait_group 0;" ::: "memory"); }

// packed f32x2 helpers
__device__ __forceinline__ u64t dup2(float a) {
    u64t d; asm("mov.b64 %0, {%1, %1};" : "=l"(d) : "f"(a)); return d;
}
__device__ __forceinline__ float2 unpk(u64t v) {
    float2 r; asm("mov.b64 {%0, %1}, %2;" : "=f"(r.x), "=f"(r.y) : "l"(v)); return r;
}
#define FMA2(acc, a, b) asm("fma.rn.f32x2 %0, %1, %2, %0;" : "+l"(acc) : "l"(a), "l"(b))

// C[32 x 128] (+)= sIn[32 x 32*NSL] @ gW[32*NSL x 128]
// Thread (rg = tid>>5 -> rows rg*4..+3, c0 = (tid&31)*4 -> cols c0..+3).
// Accumulators: packed f32x2 pairs acc[4 rows][2 col-pairs]. Barriers uniform.
template <int NSL>
__device__ __forceinline__ void gemm_block(
    const float* __restrict__ gW, int ldw,
    const float* __restrict__ sIn, int ldin,
    float* __restrict__ sW,
    u64t (&acc)[4][2], int rg, int c0)
{
    __syncthreads();   // protect sW buffers; make sIn writes visible

    // preload slice 0 into buffer 0
#pragma unroll
    for (int q = 0; q < 4; q++) {
        int r = q * 8 + rg;
        cp16(sW + r * 128 + c0, gW + (size_t)r * ldw + c0);
    }
    cp_commit();

#pragma unroll 1
    for (int t = 0; t < NSL; t++) {
        cp_wait0();        // slice t landed
        __syncthreads();   // visible to all; all warps done with prior slice

        if (t + 1 < NSL) {
            const float* g = gW + (size_t)(t + 1) * 32 * ldw;
            float* buf = sW + ((t + 1) & 1) * 4096;
#pragma unroll
            for (int q = 0; q < 4; q++) {
                int r = q * 8 + rg;
                cp16(buf + r * 128 + c0, g + (size_t)r * ldw + c0);
            }
            cp_commit();
        }

        const float* buf = sW + (t & 1) * 4096;
        const float* Ab  = sIn + (rg * 4) * ldin + t * 32;
#pragma unroll
        for (int k4 = 0; k4 < 32; k4 += 4) {
            float4 a0 = *(const float4*)(Ab + 0 * ldin + k4);
            float4 a1 = *(const float4*)(Ab + 1 * ldin + k4);
            float4 a2 = *(const float4*)(Ab + 2 * ldin + k4);
            float4 a3 = *(const float4*)(Ab + 3 * ldin + k4);
#pragma unroll
            for (int u = 0; u < 4; u++) {
                ulonglong2 w = *(const ulonglong2*)(buf + (k4 + u) * 128 + c0);
                u64t d0 = dup2((&a0.x)[u]);
                u64t d1 = dup2((&a1.x)[u]);
                u64t d2 = dup2((&a2.x)[u]);
                u64t d3 = dup2((&a3.x)[u]);
                FMA2(acc[0][0], d0, w.x); FMA2(acc[0][1], d0, w.y);
                FMA2(acc[1][0], d1, w.x); FMA2(acc[1][1], d1, w.y);
                FMA2(acc[2][0], d2, w.x); FMA2(acc[2][1], d2, w.y);
                FMA2(acc[3][0], d3, w.x); FMA2(acc[3][1], d3, w.y);
            }
        }
    }
}

__global__ __launch_bounds__(256, 2)
void ode_fused(const float* __restrict__ y0, const float* __restrict__ ts,
               const float* __restrict__ W1, const float* __restrict__ b1,
               const float* __restrict__ W2, const float* __restrict__ b2,
               const float* __restrict__ W3, const float* __restrict__ b3,
               float* __restrict__ out)
{
    extern __shared__ float sm[];
    float* sXT = sm + OFF_XT;   // stage input x (L1); h2 chunk t (L2/L3)
    float* sH  = sm + OFF_H;
    float* sW  = sm + OFF_W;

    const int tid  = threadIdx.x;
    const int rg   = tid >> 5;          // warp 0..7 -> rows rg*4..+3
    const int c0   = (tid & 31) * 4;    // col base 0..124
    const int r0   = rg * 4;
    const int grow = blockIdx.x * BM + r0;

    const float dt = (ts[1] - ts[0]) * (1.0f / NSTEPS);

    // y in registers: 4 rows x 4 cols per thread
    float y[4][4];
#pragma unroll
    for (int i = 0; i < 4; i++) {
        float4 v = *(const float4*)(y0 + (size_t)(grow + i) * 128 + c0);
        y[i][0] = v.x; y[i][1] = v.y; y[i][2] = v.z; y[i][3] = v.w;
    }

    // this thread's k-scratch base ([6][8192][128])
    float* kbase = g_k + (size_t)(grow) * 128 + c0;
#define KPTR(j, i) (kbase + (size_t)(j) * 8192 * 128 + (i) * 128)

#pragma unroll 1
    for (int step = 0; step < NSTEPS; step++) {
#pragma unroll 1
        for (int s = 0; s < 6; s++) {
            // prior stage's L3 reads of sXT (as sT) must be complete
            __syncthreads();

            // ---- stage input x = y + dt * sum_{j<s} A[s][j] * k_j  -> sXT
#pragma unroll
            for (int i = 0; i < 4; i++) {
                float4 x = make_float4(y[i][0], y[i][1], y[i][2], y[i][3]);
#pragma unroll 1
                for (int j = 0; j < s; j++) {
                    float cj = dt * c_A[s][j];
                    float4 kv = *(const float4*)KPTR(j, i);
                    x.x = fmaf(cj, kv.x, x.x);
                    x.y = fmaf(cj, kv.y, x.y);
                    x.z = fmaf(cj, kv.z, x.z);
                    x.w = fmaf(cj, kv.w, x.w);
                }
                *(float4*)(sXT + (r0 + i) * 128 + c0) = x;
            }

            // ---- layer 1: h1 = tanh(x @ W1 + b1)   [32x128]@[128x512]
#pragma unroll 1
            for (int nc = 0; nc < 4; nc++) {
                u64t acc[4][2] = {};
                gemm_block<4>(W1 + nc * 128, 512, sXT, 128, sW, acc, rg, c0);
                float4 bb = *(const float4*)(b1 + nc * 128 + c0);
#pragma unroll
                for (int i = 0; i < 4; i++) {
                    float2 p0 = unpk(acc[i][0]);
                    float2 p1 = unpk(acc[i][1]);
                    float4 r;
                    r.x = tanhf(p0.x + bb.x);
                    r.y = tanhf(p0.y + bb.y);
                    r.z = tanhf(p1.x + bb.z);
                    r.w = tanhf(p1.y + bb.w);
                    *(float4*)(sH + (r0 + i) * 512 + nc * 128 + c0) = r;
                }
            }

            // ---- layer 2 + 3 fused: per h2 chunk, t=tanh(h1@W2c+b2c); kacc += t@W3c
            u64t kacc[4][2] = {};
#pragma unroll 1
            for (int nc = 0; nc < 4; nc++) {
                u64t acc[4][2] = {};
                gemm_block<16>(W2 + nc * 128, 512, sH, 512, sW, acc, rg, c0);
                float4 bb = *(const float4*)(b2 + nc * 128 + c0);
#pragma unroll
                for (int i = 0; i < 4; i++) {
                    float2 p0 = unpk(acc[i][0]);
                    float2 p1 = unpk(acc[i][1]);
                    float4 r;
                    r.x = tanhf(p0.x + bb.x);
                    r.y = tanhf(p0.y + bb.y);
                    r.z = tanhf(p1.x + bb.z);
                    r.w = tanhf(p1.y + bb.w);
                    *(float4*)(sXT + (r0 + i) * 128 + c0) = r;  // sT
                }
                // leading __syncthreads inside gemm_block makes sT visible
                gemm_block<4>(W3 + (size_t)nc * 128 * 128, 128, sXT, 128, sW, kacc, rg, c0);
            }

            // ---- k_s = kacc + b3 -> global scratch (thread-local positions)
            {
                float4 b3v = *(const float4*)(b3 + c0);
#pragma unroll
                for (int i = 0; i < 4; i++) {
                    float2 p0 = unpk(kacc[i][0]);
                    float2 p1 = unpk(kacc[i][1]);
                    float4 kv;
                    kv.x = p0.x + b3v.x;
                    kv.y = p0.y + b3v.y;
                    kv.z = p1.x + b3v.z;
                    kv.w = p1.y + b3v.w;
                    *(float4*)KPTR(s, i) = kv;
                }
            }
        }

        // ---- y += dt * sum_j B[j] * k_j (thread-local reads; same-thread RAW)
#pragma unroll
        for (int i = 0; i < 4; i++) {
            float4 a = make_float4(0.f, 0.f, 0.f, 0.f);
#pragma unroll
            for (int j = 0; j < 6; j++) {
                float cj = c_B[j];
                float4 kv = *(const float4*)KPTR(j, i);
                a.x = fmaf(cj, kv.x, a.x);
                a.y = fmaf(cj, kv.y, a.y);
                a.z = fmaf(cj, kv.z, a.z);
                a.w = fmaf(cj, kv.w, a.w);
            }
            y[i][0] = fmaf(dt, a.x, y[i][0]);
            y[i][1] = fmaf(dt, a.y, y[i][1]);
            y[i][2] = fmaf(dt, a.z, y[i][2]);
            y[i][3] = fmaf(dt, a.w, y[i][3]);
        }
    }

    // final write
#pragma unroll
    for (int i = 0; i < 4; i++) {
        float4 v = make_float4(y[i][0], y[i][1], y[i][2], y[i][3]);
        *(float4*)(out + (size_t)(grow + i) * 128 + c0) = v;
    }
#undef KPTR
}

extern "C" void kernel_launch(void* const* d_in, const int* in_sizes, int n_in,
                              void* d_out, int out_size)
{
    const float* y0 = (const float*)d_in[0];
    const float* ts = (const float*)d_in[1];
    const float* W1 = (const float*)d_in[2];
    const float* b1 = (const float*)d_in[3];
    const float* W2 = (const float*)d_in[4];
    const float* b2 = (const float*)d_in[5];
    const float* W3 = (const float*)d_in[6];
    const float* b3 = (const float*)d_in[7];
    float* out = (float*)d_out;

    const int smem_bytes = SMEM_FLOATS * (int)sizeof(float);  // 114688 -> 2 CTAs/SM
    cudaFuncSetAttribute(ode_fused, cudaFuncAttributeMaxDynamicSharedMemorySize, smem_bytes);

    // single kernel launch = single graph node
    ode_fused<<<GRID, 256, smem_bytes>>>(y0, ts, W1, b1, W2, b2, W3, b3, out);
}

// round 13
// speedup vs baseline: 1.0005x; 1.0005x over previous
#include <cuda_runtime.h>
#include <math.h>

#define NSTEPS 64
#define BM     32
#define GRID   256   // 8192 / 32

// Tsit5 tableau in constant memory
__constant__ float c_A[6][5] = {
    {0.f, 0.f, 0.f, 0.f, 0.f},
    {0.161f, 0.f, 0.f, 0.f, 0.f},
    {-0.008480655492356989f, 0.335480655492357f, 0.f, 0.f, 0.f},
    {2.8971530571054935f, -6.359448489975075f, 4.3622954328695815f, 0.f, 0.f},
    {5.325864828439257f, -11.748883564062828f, 7.4955393428898365f, -0.09249506636175525f, 0.f},
    {5.86145544294642f, -12.92096931784711f, 8.159367898576159f, -0.071584973281401f, -0.028269050394068383f},
};
__constant__ float c_B[6] = {
    0.09646076681806523f, 0.01f, 0.4798896504144996f,
    1.379008574103742f, -3.290069515436081f, 2.324710524099774f
};

// k stages in global scratch (L2-resident, 25 MB), strictly thread-local access
__device__ float g_k[6 * 8192 * 128];

// SMEM (floats) per CTA: sXT[32*128] | sH[32*512] | sW[2*32*128]  = 112 KB
#define OFF_XT 0
#define OFF_H  4096
#define OFF_W  20480
#define SMEM_FLOATS 28672   // 112 KB -> 2 CTAs/SM

typedef unsigned long long u64t;

__device__ __forceinline__ void cp16(float* dst, const float* src) {
    unsigned d = (unsigned)__cvta_generic_to_shared(dst);
    asm volatile("cp.async.cg.shared.global [%0], [%1], 16;" :: "r"(d), "l"(src));
}
__device__ __forceinline__ void cp_commit() { asm volatile("cp.async.commit_group;"); }
__device__ __forceinline__ void cp_wait0()  { asm volatile("cp.async.wait_group 0;" ::: "memory"); }

// packed f32x2 helpers
__device__ __forceinline__ u64t dup2(float a) {
    u64t d; asm("mov.b64 %0, {%1, %1};" : "=l"(d) : "f"(a)); return d;
}
__device__ __forceinline__ float2 unpk(u64t v) {
    float2 r; asm("mov.b64 {%0, %1}, %2;" : "=f"(r.x), "=f"(r.y) : "l"(v)); return r;
}
#define FMA2(acc, a, b) asm("fma.rn.f32x2 %0, %1, %2, %0;" : "+l"(acc) : "l"(a), "l"(b))

// C[32 x 128] (+)= sIn[32 x 32*NSL] @ gW[32*NSL x 128]
// Thread (rg = tid>>5 -> rows rg*4..+3, c0 = (tid&31)*4 -> cols c0..+3).
// Accumulators: packed f32x2 pairs acc[4 rows][2 col-pairs]. Barriers uniform.
template <int NSL>
__device__ __forceinline__ void gemm_block(
    const float* __restrict__ gW, int ldw,
    const float* __restrict__ sIn, int ldin,
    float* __restrict__ sW,
    u64t (&acc)[4][2], int rg, int c0)
{
    __syncthreads();   // protect sW buffers; make sIn writes visible

    // preload slice 0 into buffer 0
#pragma unroll
    for (int q = 0; q < 4; q++) {
        int r = q * 8 + rg;
        cp16(sW + r * 128 + c0, gW + (size_t)r * ldw + c0);
    }
    cp_commit();

#pragma unroll 1
    for (int t = 0; t < NSL; t++) {
        cp_wait0();        // slice t landed
        __syncthreads();   // visible to all; all warps done with prior slice

        if (t + 1 < NSL) {
            const float* g = gW + (size_t)(t + 1) * 32 * ldw;
            float* buf = sW + ((t + 1) & 1) * 4096;
#pragma unroll
            for (int q = 0; q < 4; q++) {
                int r = q * 8 + rg;
                cp16(buf + r * 128 + c0, g + (size_t)r * ldw + c0);
            }
            cp_commit();
        }

        const float* buf = sW + (t & 1) * 4096;
        const float* Ab  = sIn + (rg * 4) * ldin + t * 32;
#pragma unroll
        for (int k4 = 0; k4 < 32; k4 += 4) {
            float4 a0 = *(const float4*)(Ab + 0 * ldin + k4);
            float4 a1 = *(const float4*)(Ab + 1 * ldin + k4);
            float4 a2 = *(const float4*)(Ab + 2 * ldin + k4);
            float4 a3 = *(const float4*)(Ab + 3 * ldin + k4);
#pragma unroll
            for (int u = 0; u < 4; u++) {
                ulonglong2 w = *(const ulonglong2*)(buf + (k4 + u) * 128 + c0);
                u64t d0 = dup2((&a0.x)[u]);
                u64t d1 = dup2((&a1.x)[u]);
                u64t d2 = dup2((&a2.x)[u]);
                u64t d3 = dup2((&a3.x)[u]);
                FMA2(acc[0][0], d0, w.x); FMA2(acc[0][1], d0, w.y);
                FMA2(acc[1][0], d1, w.x); FMA2(acc[1][1], d1, w.y);
                FMA2(acc[2][0], d2, w.x); FMA2(acc[2][1], d2, w.y);
                FMA2(acc[3][0], d3, w.x); FMA2(acc[3][1], d3, w.y);
            }
        }
    }
}

__global__ __launch_bounds__(256, 2)
void ode_fused(const float* __restrict__ y0, const float* __restrict__ ts,
               const float* __restrict__ W1, const float* __restrict__ b1,
               const float* __restrict__ W2, const float* __restrict__ b2,
               const float* __restrict__ W3, const float* __restrict__ b3,
               float* __restrict__ out)
{
    extern __shared__ float sm[];
    float* sXT = sm + OFF_XT;   // stage input x (L1); h2 chunk t (L2/L3)
    float* sH  = sm + OFF_H;
    float* sW  = sm + OFF_W;

    const int tid  = threadIdx.x;
    const int rg   = tid >> 5;          // warp 0..7 -> rows rg*4..+3
    const int c0   = (tid & 31) * 4;    // col base 0..124
    const int r0   = rg * 4;
    const int grow = blockIdx.x * BM + r0;

    const float dt = (ts[1] - ts[0]) * (1.0f / NSTEPS);

    // y in registers: 4 rows x 4 cols per thread
    float y[4][4];
#pragma unroll
    for (int i = 0; i < 4; i++) {
        float4 v = *(const float4*)(y0 + (size_t)(grow + i) * 128 + c0);
        y[i][0] = v.x; y[i][1] = v.y; y[i][2] = v.z; y[i][3] = v.w;
    }

    // this thread's k-scratch base ([6][8192][128])
    float* kbase = g_k + (size_t)(grow) * 128 + c0;
#define KPTR(j, i) (kbase + (size_t)(j) * 8192 * 128 + (i) * 128)

#pragma unroll 1
    for (int step = 0; step < NSTEPS; step++) {
#pragma unroll 1
        for (int s = 0; s < 6; s++) {
            // prior stage's L3 reads of sXT (as sT) must be complete
            __syncthreads();

            // ---- stage input x = y + dt * sum_{j<s} A[s][j] * k_j  -> sXT
#pragma unroll
            for (int i = 0; i < 4; i++) {
                float4 x = make_float4(y[i][0], y[i][1], y[i][2], y[i][3]);
#pragma unroll 1
                for (int j = 0; j < s; j++) {
                    float cj = dt * c_A[s][j];
                    float4 kv = *(const float4*)KPTR(j, i);
                    x.x = fmaf(cj, kv.x, x.x);
                    x.y = fmaf(cj, kv.y, x.y);
                    x.z = fmaf(cj, kv.z, x.z);
                    x.w = fmaf(cj, kv.w, x.w);
                }
                *(float4*)(sXT + (r0 + i) * 128 + c0) = x;
            }

            // ---- layer 1: h1 = tanh(x @ W1 + b1)   [32x128]@[128x512]
#pragma unroll 1
            for (int nc = 0; nc < 4; nc++) {
                u64t acc[4][2] = {};
                gemm_block<4>(W1 + nc * 128, 512, sXT, 128, sW, acc, rg, c0);
                float4 bb = *(const float4*)(b1 + nc * 128 + c0);
#pragma unroll
                for (int i = 0; i < 4; i++) {
                    float2 p0 = unpk(acc[i][0]);
                    float2 p1 = unpk(acc[i][1]);
                    float4 r;
                    r.x = tanhf(p0.x + bb.x);
                    r.y = tanhf(p0.y + bb.y);
                    r.z = tanhf(p1.x + bb.z);
                    r.w = tanhf(p1.y + bb.w);
                    *(float4*)(sH + (r0 + i) * 512 + nc * 128 + c0) = r;
                }
            }

            // ---- layer 2 + 3 fused: per h2 chunk, t=tanh(h1@W2c+b2c); kacc += t@W3c
            u64t kacc[4][2] = {};
#pragma unroll 1
            for (int nc = 0; nc < 4; nc++) {
                u64t acc[4][2] = {};
                gemm_block<16>(W2 + nc * 128, 512, sH, 512, sW, acc, rg, c0);
                float4 bb = *(const float4*)(b2 + nc * 128 + c0);
#pragma unroll
                for (int i = 0; i < 4; i++) {
                    float2 p0 = unpk(acc[i][0]);
                    float2 p1 = unpk(acc[i][1]);
                    float4 r;
                    r.x = tanhf(p0.x + bb.x);
                    r.y = tanhf(p0.y + bb.y);
                    r.z = tanhf(p1.x + bb.z);
                    r.w = tanhf(p1.y + bb.w);
                    *(float4*)(sXT + (r0 + i) * 128 + c0) = r;  // sT
                }
                // leading __syncthreads inside gemm_block makes sT visible
                gemm_block<4>(W3 + (size_t)nc * 128 * 128, 128, sXT, 128, sW, kacc, rg, c0);
            }

            // ---- k_s = kacc + b3 -> global scratch (thread-local positions)
            {
                float4 b3v = *(const float4*)(b3 + c0);
#pragma unroll
                for (int i = 0; i < 4; i++) {
                    float2 p0 = unpk(kacc[i][0]);
                    float2 p1 = unpk(kacc[i][1]);
                    float4 kv;
                    kv.x = p0.x + b3v.x;
                    kv.y = p0.y + b3v.y;
                    kv.z = p1.x + b3v.z;
                    kv.w = p1.y + b3v.w;
                    *(float4*)KPTR(s, i) = kv;
                }
            }
        }

        // ---- y += dt * sum_j B[j] * k_j (thread-local reads; same-thread RAW)
#pragma unroll
        for (int i = 0; i < 4; i++) {
            float4 a = make_float4(0.f, 0.f, 0.f, 0.f);
#pragma unroll
            for (int j = 0; j < 6; j++) {
                float cj = c_B[j];
                float4 kv = *(const float4*)KPTR(j, i);
                a.x = fmaf(cj, kv.x, a.x);
                a.y = fmaf(cj, kv.y, a.y);
                a.z = fmaf(cj, kv.z, a.z);
                a.w = fmaf(cj, kv.w, a.w);
            }
            y[i][0] = fmaf(dt, a.x, y[i][0]);
            y[i][1] = fmaf(dt, a.y, y[i][1]);
            y[i][2] = fmaf(dt, a.z, y[i][2]);
            y[i][3] = fmaf(dt, a.w, y[i][3]);
        }
    }

    // final write
#pragma unroll
    for (int i = 0; i < 4; i++) {
        float4 v = make_float4(y[i][0], y[i][1], y[i][2], y[i][3]);
        *(float4*)(out + (size_t)(grow + i) * 128 + c0) = v;
    }
#undef KPTR
}

extern "C" void kernel_launch(void* const* d_in, const int* in_sizes, int n_in,
                              void* d_out, int out_size)
{
    const float* y0 = (const float*)d_in[0];
    const float* ts = (const float*)d_in[1];
    const float* W1 = (const float*)d_in[2];
    const float* b1 = (const float*)d_in[3];
    const float* W2 = (const float*)d_in[4];
    const float* b2 = (const float*)d_in[5];
    const float* W3 = (const float*)d_in[6];
    const float* b3 = (const float*)d_in[7];
    float* out = (float*)d_out;

    const int smem_bytes = SMEM_FLOATS * (int)sizeof(float);  // 114688 -> 2 CTAs/SM
    cudaFuncSetAttribute(ode_fused, cudaFuncAttributeMaxDynamicSharedMemorySize, smem_bytes);

    // single kernel launch = single graph node
    ode_fused<<<GRID, 256, smem_bytes>>>(y0, ts, W1, b1, W2, b2, W3, b3, out);
}

// round 14
// speedup vs baseline: 1.0034x; 1.0029x over previous
#include <cuda_runtime.h>
#include <math.h>

#define NSTEPS 64
#define BM     32
#define GRID   256   // 8192 / 32

// Tsit5 tableau in constant memory
__constant__ float c_A[6][5] = {
    {0.f, 0.f, 0.f, 0.f, 0.f},
    {0.161f, 0.f, 0.f, 0.f, 0.f},
    {-0.008480655492356989f, 0.335480655492357f, 0.f, 0.f, 0.f},
    {2.8971530571054935f, -6.359448489975075f, 4.3622954328695815f, 0.f, 0.f},
    {5.325864828439257f, -11.748883564062828f, 7.4955393428898365f, -0.09249506636175525f, 0.f},
    {5.86145544294642f, -12.92096931784711f, 8.159367898576159f, -0.071584973281401f, -0.028269050394068383f},
};
__constant__ float c_B[6] = {
    0.09646076681806523f, 0.01f, 0.4798896504144996f,
    1.379008574103742f, -3.290069515436081f, 2.324710524099774f
};

// k stages in global scratch (L2-resident, 25 MB), strictly thread-local access
__device__ float g_k[6 * 8192 * 128];

// SMEM (floats) per CTA: sXT[32*128] | sH[32*512] | sW[2*32*128]  = 112 KB
#define OFF_XT 0
#define OFF_H  4096
#define OFF_W  20480
#define SMEM_FLOATS 28672   // 112 KB -> 2 CTAs/SM

typedef unsigned long long u64t;

__device__ __forceinline__ void cp16(float* dst, const float* src) {
    unsigned d = (unsigned)__cvta_generic_to_shared(dst);
    asm volatile("cp.async.cg.shared.global [%0], [%1], 16;" :: "r"(d), "l"(src));
}
__device__ __forceinline__ void cp_commit() { asm volatile("cp.async.commit_group;"); }
__device__ __forceinline__ void cp_wait0()  { asm volatile("cp.async.wait_group 0;" ::: "memory"); }

// packed f32x2 helpers
__device__ __forceinline__ u64t dup2(float a) {
    u64t d; asm("mov.b64 %0, {%1, %1};" : "=l"(d) : "f"(a)); return d;
}
__device__ __forceinline__ float2 unpk(u64t v) {
    float2 r; asm("mov.b64 {%0, %1}, %2;" : "=f"(r.x), "=f"(r.y) : "l"(v)); return r;
}
#define FMA2(acc, a, b) asm("fma.rn.f32x2 %0, %1, %2, %0;" : "+l"(acc) : "l"(a), "l"(b))

// C[32 x 128] (+)= sIn[32 x 32*NSL] @ gW[32*NSL x 128]
// Thread (rg = tid>>5 -> rows rg*4..+3, c0 = (tid&31)*4 -> cols c0..+3).
// Accumulators: packed f32x2 pairs acc[4 rows][2 col-pairs]. Barriers uniform.
template <int NSL>
__device__ __forceinline__ void gemm_block(
    const float* __restrict__ gW, int ldw,
    const float* __restrict__ sIn, int ldin,
    float* __restrict__ sW,
    u64t (&acc)[4][2], int rg, int c0)
{
    __syncthreads();   // protect sW buffers; make sIn writes visible

    // preload slice 0 into buffer 0
#pragma unroll
    for (int q = 0; q < 4; q++) {
        int r = q * 8 + rg;
        cp16(sW + r * 128 + c0, gW + (size_t)r * ldw + c0);
    }
    cp_commit();

#pragma unroll 1
    for (int t = 0; t < NSL; t++) {
        cp_wait0();        // slice t landed
        __syncthreads();   // visible to all; all warps done with prior slice

        if (t + 1 < NSL) {
            const float* g = gW + (size_t)(t + 1) * 32 * ldw;
            float* buf = sW + ((t + 1) & 1) * 4096;
#pragma unroll
            for (int q = 0; q < 4; q++) {
                int r = q * 8 + rg;
                cp16(buf + r * 128 + c0, g + (size_t)r * ldw + c0);
            }
            cp_commit();
        }

        const float* buf = sW + (t & 1) * 4096;
        const float* Ab  = sIn + (rg * 4) * ldin + t * 32;
#pragma unroll
        for (int k4 = 0; k4 < 32; k4 += 4) {
            float4 a0 = *(const float4*)(Ab + 0 * ldin + k4);
            float4 a1 = *(const float4*)(Ab + 1 * ldin + k4);
            float4 a2 = *(const float4*)(Ab + 2 * ldin + k4);
            float4 a3 = *(const float4*)(Ab + 3 * ldin + k4);
#pragma unroll
            for (int u = 0; u < 4; u++) {
                ulonglong2 w = *(const ulonglong2*)(buf + (k4 + u) * 128 + c0);
                u64t d0 = dup2((&a0.x)[u]);
                u64t d1 = dup2((&a1.x)[u]);
                u64t d2 = dup2((&a2.x)[u]);
                u64t d3 = dup2((&a3.x)[u]);
                FMA2(acc[0][0], d0, w.x); FMA2(acc[0][1], d0, w.y);
                FMA2(acc[1][0], d1, w.x); FMA2(acc[1][1], d1, w.y);
                FMA2(acc[2][0], d2, w.x); FMA2(acc[2][1], d2, w.y);
                FMA2(acc[3][0], d3, w.x); FMA2(acc[3][1], d3, w.y);
            }
        }
    }
}

__global__ __launch_bounds__(256, 2)
void ode_fused(const float* __restrict__ y0, const float* __restrict__ ts,
               const float* __restrict__ W1, const float* __restrict__ b1,
               const float* __restrict__ W2, const float* __restrict__ b2,
               const float* __restrict__ W3, const float* __restrict__ b3,
               float* __restrict__ out)
{
    extern __shared__ float sm[];
    float* sXT = sm + OFF_XT;   // stage input x (L1); h2 chunk t (L2/L3)
    float* sH  = sm + OFF_H;
    float* sW  = sm + OFF_W;

    const int tid  = threadIdx.x;
    const int rg   = tid >> 5;          // warp 0..7 -> rows rg*4..+3
    const int c0   = (tid & 31) * 4;    // col base 0..124
    const int r0   = rg * 4;
    const int grow = blockIdx.x * BM + r0;

    const float dt = (ts[1] - ts[0]) * (1.0f / NSTEPS);

    // y in registers: 4 rows x 4 cols per thread
    float y[4][4];
#pragma unroll
    for (int i = 0; i < 4; i++) {
        float4 v = *(const float4*)(y0 + (size_t)(grow + i) * 128 + c0);
        y[i][0] = v.x; y[i][1] = v.y; y[i][2] = v.z; y[i][3] = v.w;
    }

    // this thread's k-scratch base ([6][8192][128])
    float* kbase = g_k + (size_t)(grow) * 128 + c0;
#define KPTR(j, i) (kbase + (size_t)(j) * 8192 * 128 + (i) * 128)

#pragma unroll 1
    for (int step = 0; step < NSTEPS; step++) {
#pragma unroll 1
        for (int s = 0; s < 6; s++) {
            // prior stage's L3 reads of sXT (as sT) must be complete
            __syncthreads();

            // ---- stage input x = y + dt * sum_{j<s} A[s][j] * k_j  -> sXT
#pragma unroll
            for (int i = 0; i < 4; i++) {
                float4 x = make_float4(y[i][0], y[i][1], y[i][2], y[i][3]);
#pragma unroll 1
                for (int j = 0; j < s; j++) {
                    float cj = dt * c_A[s][j];
                    float4 kv = *(const float4*)KPTR(j, i);
                    x.x = fmaf(cj, kv.x, x.x);
                    x.y = fmaf(cj, kv.y, x.y);
                    x.z = fmaf(cj, kv.z, x.z);
                    x.w = fmaf(cj, kv.w, x.w);
                }
                *(float4*)(sXT + (r0 + i) * 128 + c0) = x;
            }

            // ---- layer 1: h1 = tanh(x @ W1 + b1)   [32x128]@[128x512]
#pragma unroll 1
            for (int nc = 0; nc < 4; nc++) {
                u64t acc[4][2] = {};
                gemm_block<4>(W1 + nc * 128, 512, sXT, 128, sW, acc, rg, c0);
                float4 bb = *(const float4*)(b1 + nc * 128 + c0);
#pragma unroll
                for (int i = 0; i < 4; i++) {
                    float2 p0 = unpk(acc[i][0]);
                    float2 p1 = unpk(acc[i][1]);
                    float4 r;
                    r.x = tanhf(p0.x + bb.x);
                    r.y = tanhf(p0.y + bb.y);
                    r.z = tanhf(p1.x + bb.z);
                    r.w = tanhf(p1.y + bb.w);
                    *(float4*)(sH + (r0 + i) * 512 + nc * 128 + c0) = r;
                }
            }

            // ---- layer 2 + 3 fused: per h2 chunk, t=tanh(h1@W2c+b2c); kacc += t@W3c
            u64t kacc[4][2] = {};
#pragma unroll 1
            for (int nc = 0; nc < 4; nc++) {
                u64t acc[4][2] = {};
                gemm_block<16>(W2 + nc * 128, 512, sH, 512, sW, acc, rg, c0);
                float4 bb = *(const float4*)(b2 + nc * 128 + c0);
#pragma unroll
                for (int i = 0; i < 4; i++) {
                    float2 p0 = unpk(acc[i][0]);
                    float2 p1 = unpk(acc[i][1]);
                    float4 r;
                    r.x = tanhf(p0.x + bb.x);
                    r.y = tanhf(p0.y + bb.y);
                    r.z = tanhf(p1.x + bb.z);
                    r.w = tanhf(p1.y + bb.w);
                    *(float4*)(sXT + (r0 + i) * 128 + c0) = r;  // sT
                }
                // leading __syncthreads inside gemm_block makes sT visible
                gemm_block<4>(W3 + (size_t)nc * 128 * 128, 128, sXT, 128, sW, kacc, rg, c0);
            }

            // ---- k_s = kacc + b3 -> global scratch (thread-local positions)
            {
                float4 b3v = *(const float4*)(b3 + c0);
#pragma unroll
                for (int i = 0; i < 4; i++) {
                    float2 p0 = unpk(kacc[i][0]);
                    float2 p1 = unpk(kacc[i][1]);
                    float4 kv;
                    kv.x = p0.x + b3v.x;
                    kv.y = p0.y + b3v.y;
                    kv.z = p1.x + b3v.z;
                    kv.w = p1.y + b3v.w;
                    *(float4*)KPTR(s, i) = kv;
                }
            }
        }

        // ---- y += dt * sum_j B[j] * k_j (thread-local reads; same-thread RAW)
#pragma unroll
        for (int i = 0; i < 4; i++) {
            float4 a = make_float4(0.f, 0.f, 0.f, 0.f);
#pragma unroll
            for (int j = 0; j < 6; j++) {
                float cj = c_B[j];
                float4 kv = *(const float4*)KPTR(j, i);
                a.x = fmaf(cj, kv.x, a.x);
                a.y = fmaf(cj, kv.y, a.y);
                a.z = fmaf(cj, kv.z, a.z);
                a.w = fmaf(cj, kv.w, a.w);
            }
            y[i][0] = fmaf(dt, a.x, y[i][0]);
            y[i][1] = fmaf(dt, a.y, y[i][1]);
            y[i][2] = fmaf(dt, a.z, y[i][2]);
            y[i][3] = fmaf(dt, a.w, y[i][3]);
        }
    }

    // final write
#pragma unroll
    for (int i = 0; i < 4; i++) {
        float4 v = make_float4(y[i][0], y[i][1], y[i][2], y[i][3]);
        *(float4*)(out + (size_t)(grow + i) * 128 + c0) = v;
    }
#undef KPTR
}

extern "C" void kernel_launch(void* const* d_in, const int* in_sizes, int n_in,
                              void* d_out, int out_size)
{
    const float* y0 = (const float*)d_in[0];
    const float* ts = (const float*)d_in[1];
    const float* W1 = (const float*)d_in[2];
    const float* b1 = (const float*)d_in[3];
    const float* W2 = (const float*)d_in[4];
    const float* b2 = (const float*)d_in[5];
    const float* W3 = (const float*)d_in[6];
    const float* b3 = (const float*)d_in[7];
    float* out = (float*)d_out;

    const int smem_bytes = SMEM_FLOATS * (int)sizeof(float);  // 114688 -> 2 CTAs/SM
    cudaFuncSetAttribute(ode_fused, cudaFuncAttributeMaxDynamicSharedMemorySize, smem_bytes);

    // single kernel launch = single graph node
    ode_fused<<<GRID, 256, smem_bytes>>>(y0, ts, W1, b1, W2, b2, W3, b3, out);
}

// round 16
// speedup vs baseline: 1.3871x; 1.3823x over previous
#include <cuda_runtime.h>
#include <cuda_bf16.h>
#include <math.h>
#include <stdint.h>

#define NSTEPS 64
typedef unsigned int u32;
typedef unsigned short u16;

__constant__ float c_A[6][5] = {
    {0.f,0.f,0.f,0.f,0.f},
    {0.161f,0.f,0.f,0.f,0.f},
    {-0.008480655492356989f,0.335480655492357f,0.f,0.f,0.f},
    {2.8971530571054935f,-6.359448489975075f,4.3622954328695815f,0.f,0.f},
    {5.325864828439257f,-11.748883564062828f,7.4955393428898365f,-0.09249506636175525f,0.f},
    {5.86145544294642f,-12.92096931784711f,8.159367898576159f,-0.071584973281401f,-0.028269050394068383f},
};
__constant__ float c_B6[6] = {
    0.09646076681806523f,0.01f,0.4798896504144996f,
    1.379008574103742f,-3.290069515436081f,2.324710524099774f
};

// global scratch
__device__ float g_y[8192 * 128];
__device__ float g_k[6ll * 8192 * 128];
// pre-split, pre-swizzled W chunk images: each chunk [64k x 128n] bf16 = 16384 B
__device__ u16 g_w1h[65536],  g_w1l[65536];    // 8 chunks  (nc*2+ks)
__device__ u16 g_w2h[262144], g_w2l[262144];   // 32 chunks (nc*8+ks)
__device__ u16 g_w3h[65536],  g_w3l[65536];    // 8 chunks  (nc*2+ks)

// SMEM bytes: sX (x/t) hi+lo [64x136] pad | sH (h1) hi+lo [64x512] swizzled | W 2x(hi+lo)
#define SM_X 0          // hi 17408, lo +17408  -> 34816
#define SM_H 34816      // hi 65536, lo +65536  -> 165888
#define SM_W 165888     // buf(ks&1)*32768: hi 16384, lo +16384 -> 231424
#define SMEM_BYTES 231424

__device__ __forceinline__ u32 swz(u32 b) { return b ^ ((b >> 3) & 0x70); }
__device__ __forceinline__ u32 smem_u32(const void* p) {
    return (u32)__cvta_generic_to_shared(p);
}
__device__ __forceinline__ void cp16(char* dst, const char* src) {
    asm volatile("cp.async.cg.shared.global [%0], [%1], 16;"
                 :: "r"(smem_u32(dst)), "l"(src));
}
__device__ __forceinline__ void cp_commit() { asm volatile("cp.async.commit_group;"); }
__device__ __forceinline__ void cp_wait0()  { asm volatile("cp.async.wait_group 0;" ::: "memory"); }
__device__ __forceinline__ void cp_wait1()  { asm volatile("cp.async.wait_group 1;" ::: "memory"); }

#define LDSM4(r0,r1,r2,r3,a) \
    asm volatile("ldmatrix.sync.aligned.m8n8.x4.shared.b16 {%0,%1,%2,%3}, [%4];" \
        : "=r"(r0), "=r"(r1), "=r"(r2), "=r"(r3) : "r"(a))
#define LDSM4T(r0,r1,r2,r3,a) \
    asm volatile("ldmatrix.sync.aligned.m8n8.x4.trans.shared.b16 {%0,%1,%2,%3}, [%4];" \
        : "=r"(r0), "=r"(r1), "=r"(r2), "=r"(r3) : "r"(a))
#define MMA(cc,a0,a1,a2,a3,b0,b1) \
    asm volatile("mma.sync.aligned.m16n8k16.row.col.f32.bf16.bf16.f32 " \
        "{%0,%1,%2,%3},{%4,%5,%6,%7},{%8,%9},{%0,%1,%2,%3};" \
        : "+f"((cc)[0]), "+f"((cc)[1]), "+f"((cc)[2]), "+f"((cc)[3]) \
        : "r"(a0), "r"(a1), "r"(a2), "r"(a3), "r"(b0), "r"(b1))

__device__ __forceinline__ float tanh_fast(float x) {
    float cx = fminf(fmaxf(x, -15.f), 15.f);
    float e = __expf(2.f * cx);
    return __fdividef(e - 1.f, e + 1.f);
}
__device__ __forceinline__ u32 pack2(float a, float b, u32& lo) {
    __nv_bfloat16 h0 = __float2bfloat16(a), h1 = __float2bfloat16(b);
    __nv_bfloat16 l0 = __float2bfloat16(a - __bfloat162float(h0));
    __nv_bfloat16 l1 = __float2bfloat16(b - __bfloat162float(h1));
    lo = (u32)__bfloat16_as_ushort(l0) | ((u32)__bfloat16_as_ushort(l1) << 16);
    return (u32)__bfloat16_as_ushort(h0) | ((u32)__bfloat16_as_ushort(h1) << 16);
}

// ---- prep: split + transpose-to-chunks + swizzle W into global images ----
__global__ __launch_bounds__(256) void prep_w(const float* __restrict__ W1,
    const float* __restrict__ W2, const float* __restrict__ W3)
{
    int e = blockIdx.x * 256 + threadIdx.x;
    const float* src; u16 *dh, *dl; int N, KS, idx;
    if (e < 65536)       { src = W1; N = 512; KS = 2; idx = e;          dh = g_w1h; dl = g_w1l; }
    else if (e < 327680) { src = W2; N = 512; KS = 8; idx = e - 65536;  dh = g_w2h; dl = g_w2l; }
    else if (e < 393216) { src = W3; N = 128; KS = 8; idx = e - 327680; dh = g_w3h; dl = g_w3l; }
    else return;
    int k = idx / N, n = idx % N;
    float v = src[idx];
    int nc = n >> 7, nn = n & 127, ks = k >> 6, kk = k & 63;
    u32 off = (u32)(nc * KS + ks) * 16384u + swz((u32)kk * 256u + (u32)nn * 2u);
    __nv_bfloat16 h = __float2bfloat16(v);
    __nv_bfloat16 l = __float2bfloat16(v - __bfloat162float(h));
    *(u16*)((char*)dh + off) = __bfloat16_as_ushort(h);
    *(u16*)((char*)dl + off) = __bfloat16_as_ushort(l);
}

// ---- one [64 x 128] chunk, 3-pass split accumulate into c[8][4] ----
// A: SMEM (ASW: sH swizzled 1024B rows; else sX linear 272B rows), cols ks*64..
// W: global chunk slices (hi/lo), streamed via double-buffered cp.async.
template <int KSL, bool ASW>
__device__ void gemm_chunk(char* smem, const u16* wHi, const u16* wLo,
                           float (&c)[8][4], int lane, int wm, int wn, int tid)
{
    {   // prefetch slice 0 -> buf0
        char* d = smem + SM_W;
#pragma unroll
        for (int it = 0; it < 4; it++) {
            int i = it * 256 + tid;
            cp16(d + i * 16, (const char*)wHi + i * 16);
            cp16(d + 16384 + i * 16, (const char*)wLo + i * 16);
        }
        cp_commit();
    }
#pragma unroll 1
    for (int ks = 0; ks < KSL; ks++) {
        if (ks + 1 < KSL) {
            char* d = smem + SM_W + ((ks + 1) & 1) * 32768;
            const char* sh = (const char*)(wHi + (ks + 1) * 8192);
            const char* sl = (const char*)(wLo + (ks + 1) * 8192);
#pragma unroll
            for (int it = 0; it < 4; it++) {
                int i = it * 256 + tid;
                cp16(d + i * 16, sh + i * 16);
                cp16(d + 16384 + i * 16, sl + i * 16);
            }
            cp_commit();
            cp_wait1();
        } else {
            cp_wait0();
        }
        __syncthreads();   // slice ks visible; buf (ks+1)&1 free was ensured last iter

        u32 wb = smem_u32(smem) + SM_W + (ks & 1) * 32768;
        int ar = wm * 16 + (lane & 15);
#pragma unroll
        for (int kk = 0; kk < 4; kk++) {
            int ac = ks * 64 + kk * 16 + (lane >> 4) * 8;
            u32 aH, aL;
            if (ASW) {
                u32 off = swz((u32)ar * 1024u + (u32)ac * 2u);
                aH = smem_u32(smem) + SM_H + off;  aL = aH + 65536;
            } else {
                u32 off = (u32)ar * 272u + (u32)ac * 2u;
                aH = smem_u32(smem) + SM_X + off;  aL = aH + 17408;
            }
            u32 ah0,ah1,ah2,ah3, al0,al1,al2,al3;
            LDSM4(ah0,ah1,ah2,ah3, aH);
            LDSM4(al0,al1,al2,al3, aL);
            int wkr = kk * 16 + (lane & 15);
#pragma unroll
            for (int nt2 = 0; nt2 < 4; nt2++) {
                int nn = wn * 64 + nt2 * 16 + (lane >> 4) * 8;
                u32 woff = swz((u32)wkr * 256u + (u32)nn * 2u);
                u32 wh0,wh1,wh2,wh3, wl0,wl1,wl2,wl3;
                LDSM4T(wh0,wh1,wh2,wh3, wb + woff);
                LDSM4T(wl0,wl1,wl2,wl3, wb + 16384 + woff);
                MMA(c[nt2*2],   ah0,ah1,ah2,ah3, wh0,wh1);
                MMA(c[nt2*2],   ah0,ah1,ah2,ah3, wl0,wl1);
                MMA(c[nt2*2],   al0,al1,al2,al3, wh0,wh1);
                MMA(c[nt2*2+1], ah0,ah1,ah2,ah3, wh2,wh3);
                MMA(c[nt2*2+1], ah0,ah1,ah2,ah3, wl2,wl3);
                MMA(c[nt2*2+1], al0,al1,al2,al3, wh2,wh3);
            }
        }
        __syncthreads();   // all reads of buf ks&1 done -> next iter may overwrite
    }
}

// epilogue: bias + tanh + split -> SMEM tiles (TOH: sH swizzled, else sX linear)
template <bool TOH>
__device__ __forceinline__ void epi_act(float (&c)[8][4], const float* __restrict__ bias,
                                        int ncb, char* smem, int lane, int wm, int wn)
{
    int r0 = wm * 16 + (lane >> 2);
#pragma unroll
    for (int nt = 0; nt < 8; nt++) {
        int col = wn * 64 + nt * 8 + (lane & 3) * 2;
        float b0 = bias[ncb + col], b1 = bias[ncb + col + 1];
        float v0 = tanh_fast(c[nt][0] + b0), v1 = tanh_fast(c[nt][1] + b1);
        float v2 = tanh_fast(c[nt][2] + b0), v3 = tanh_fast(c[nt][3] + b1);
        u32 lo01, lo23;
        u32 hi01 = pack2(v0, v1, lo01), hi23 = pack2(v2, v3, lo23);
        if (TOH) {
            u32 o1 = swz((u32)r0 * 1024u + (u32)(ncb + col) * 2u);
            u32 o2 = swz((u32)(r0 + 8) * 1024u + (u32)(ncb + col) * 2u);
            *(u32*)(smem + SM_H + o1) = hi01;  *(u32*)(smem + SM_H + 65536 + o1) = lo01;
            *(u32*)(smem + SM_H + o2) = hi23;  *(u32*)(smem + SM_H + 65536 + o2) = lo23;
        } else {
            u32 o1 = (u32)r0 * 272u + (u32)col * 2u;
            u32 o2 = (u32)(r0 + 8) * 272u + (u32)col * 2u;
            *(u32*)(smem + SM_X + o1) = hi01;  *(u32*)(smem + SM_X + 17408 + o1) = lo01;
            *(u32*)(smem + SM_X + o2) = hi23;  *(u32*)(smem + SM_X + 17408 + o2) = lo23;
        }
    }
}

__global__ __launch_bounds__(256, 1)
void ode_mma(const float* __restrict__ y0, const float* __restrict__ ts,
             const float* __restrict__ b1, const float* __restrict__ b2,
             const float* __restrict__ b3, float* __restrict__ out)
{
    extern __shared__ char smem[];
    const int tid = threadIdx.x, lane = tid & 31, wid = tid >> 5;
    const int wm = wid & 3, wn = wid >> 2, cta = blockIdx.x;
    const float dt = (ts[1] - ts[0]) * (1.0f / NSTEPS);

    // combine/update mapping: row = tid>>2 (0..63), cols cb..cb+31
    const int row = tid >> 2, cb = (tid & 3) * 32;
    float* yrow = g_y + (size_t)(cta * 64 + row) * 128;
    {
        const float* src = y0 + (size_t)(cta * 64 + row) * 128;
#pragma unroll
        for (int c = 0; c < 32; c += 4)
            *(float4*)(yrow + cb + c) = *(const float4*)(src + cb + c);
    }
    float* kct = g_k + (size_t)(cta * 64) * 128;   // + j*8192*128

#pragma unroll 1
    for (int step = 0; step < NSTEPS; step++) {
#pragma unroll 1
        for (int s = 0; s < 6; s++) {
            // ---- stage input x -> sX (split bf16) ----
#pragma unroll 1
            for (int c = 0; c < 32; c += 4) {
                float4 x = *(const float4*)(yrow + cb + c);
#pragma unroll 1
                for (int j = 0; j < s; j++) {
                    float cj = dt * c_A[s][j];
                    float4 kv = *(const float4*)(kct + (size_t)j * 8192 * 128
                                                 + (size_t)row * 128 + cb + c);
                    x.x = fmaf(cj, kv.x, x.x); x.y = fmaf(cj, kv.y, x.y);
                    x.z = fmaf(cj, kv.z, x.z); x.w = fmaf(cj, kv.w, x.w);
                }
                u32 lo0, lo1;
                u32 h0 = pack2(x.x, x.y, lo0), h1 = pack2(x.z, x.w, lo1);
                u32 boff = (u32)row * 272u + (u32)(cb + c) * 2u;
                *(u32*)(smem + SM_X + boff) = h0;
                *(u32*)(smem + SM_X + boff + 4) = h1;
                *(u32*)(smem + SM_X + 17408 + boff) = lo0;
                *(u32*)(smem + SM_X + 17408 + boff + 4) = lo1;
            }
            // ---- layer 1: h1 = tanh(x@W1+b1) ----
#pragma unroll 1
            for (int nc = 0; nc < 4; nc++) {
                float cf[8][4] = {};
                gemm_chunk<2, false>(smem, g_w1h + nc * 16384, g_w1l + nc * 16384,
                                     cf, lane, wm, wn, tid);
                epi_act<true>(cf, b1, nc * 128, smem, lane, wm, wn);
            }
            // ---- layer 2+3 fused ----
            float kf[8][4] = {};
#pragma unroll 1
            for (int nc = 0; nc < 4; nc++) {
                float cf[8][4] = {};
                gemm_chunk<8, true>(smem, g_w2h + nc * 65536, g_w2l + nc * 65536,
                                    cf, lane, wm, wn, tid);
                epi_act<false>(cf, b2, nc * 128, smem, lane, wm, wn);
                gemm_chunk<2, false>(smem, g_w3h + nc * 16384, g_w3l + nc * 16384,
                                     kf, lane, wm, wn, tid);
            }
            // ---- k_s -> global ----
            {
                int r0 = wm * 16 + (lane >> 2);
                float* kb = kct + (size_t)s * 8192 * 128;
#pragma unroll
                for (int nt = 0; nt < 8; nt++) {
                    int col = wn * 64 + nt * 8 + (lane & 3) * 2;
                    float b0 = b3[col], b1v = b3[col + 1];
                    *(float2*)(kb + (size_t)r0 * 128 + col) =
                        make_float2(kf[nt][0] + b0, kf[nt][1] + b1v);
                    *(float2*)(kb + (size_t)(r0 + 8) * 128 + col) =
                        make_float2(kf[nt][2] + b0, kf[nt][3] + b1v);
                }
            }
            __syncthreads();   // k visible to combine readers (cross-thread)
        }
        // ---- y += dt * sum B[j] k_j ----
#pragma unroll 1
        for (int c = 0; c < 32; c += 4) {
            float4 y4 = *(const float4*)(yrow + cb + c);
            float4 a = make_float4(0.f, 0.f, 0.f, 0.f);
#pragma unroll
            for (int j = 0; j < 6; j++) {
                float cj = c_B6[j];
                float4 kv = *(const float4*)(kct + (size_t)j * 8192 * 128
                                             + (size_t)row * 128 + cb + c);
                a.x = fmaf(cj, kv.x, a.x); a.y = fmaf(cj, kv.y, a.y);
                a.z = fmaf(cj, kv.z, a.z); a.w = fmaf(cj, kv.w, a.w);
            }
            y4.x = fmaf(dt, a.x, y4.x); y4.y = fmaf(dt, a.y, y4.y);
            y4.z = fmaf(dt, a.z, y4.z); y4.w = fmaf(dt, a.w, y4.w);
            *(float4*)(yrow + cb + c) = y4;
        }
    }
    {
        float* o = out + (size_t)(cta * 64 + row) * 128;
#pragma unroll
        for (int c = 0; c < 32; c += 4)
            *(float4*)(o + cb + c) = *(const float4*)(yrow + cb + c);
    }
}

extern "C" void kernel_launch(void* const* d_in, const int* in_sizes, int n_in,
                              void* d_out, int out_size)
{
    const float* y0 = (const float*)d_in[0];
    const float* ts = (const float*)d_in[1];
    const float* W1 = (const float*)d_in[2];
    const float* b1 = (const float*)d_in[3];
    const float* W2 = (const float*)d_in[4];
    const float* b2 = (const float*)d_in[5];
    const float* W3 = (const float*)d_in[6];
    const float* b3 = (const float*)d_in[7];
    float* out = (float*)d_out;

    cudaFuncSetAttribute(ode_mma, cudaFuncAttributeMaxDynamicSharedMemorySize, SMEM_BYTES);
    prep_w<<<1536, 256>>>(W1, W2, W3);
    ode_mma<<<128, 256, SMEM_BYTES>>>(y0, ts, b1, b2, b3, out);
}